// round 1
// baseline (speedup 1.0000x reference)
#include <cuda_runtime.h>
#include <math.h>

// DamagedPointRepair:
//   mean  = 3x3 zero-padded box mean * coeff  (== average over in-bounds 3x3 window)
//   mask  = img > 5*mean || img > 1000
//   nsum  = 4-neighbor sum (zero padded), cnt = # valid 4-neighbors
//   out   = mask ? floor(nsum/cnt) : img
//
// 8192 x 8192 fp32. Memory-bound stencil: target ~1x read + 1x write DRAM traffic.

#define THRE_TIMES 5.0f
#define THRE_POINT 1000.0f

__device__ __forceinline__ void load6(const float* __restrict__ row, int x0, int W,
                                      bool valid, float v[6]) {
    if (valid) {
        const float4 c = *reinterpret_cast<const float4*>(row + x0);
        v[1] = c.x; v[2] = c.y; v[3] = c.z; v[4] = c.w;
        v[0] = (x0 > 0)       ? __ldg(row + x0 - 1) : 0.0f;
        v[5] = (x0 + 4 < W)   ? __ldg(row + x0 + 4) : 0.0f;
    } else {
        v[0] = v[1] = v[2] = v[3] = v[4] = v[5] = 0.0f;
    }
}

__global__ void __launch_bounds__(256)
repair_kernel(const float* __restrict__ img, float* __restrict__ out,
              int H, int W) {
    const int x0 = (blockIdx.x * blockDim.x + threadIdx.x) * 4;
    const int y  = blockIdx.y * blockDim.y + threadIdx.y;
    if (x0 >= W || y >= H) return;

    const bool has_up = (y > 0);
    const bool has_dn = (y < H - 1);

    const float* rowm = img + (size_t)(y - 1) * W;
    const float* row0 = img + (size_t)y * W;
    const float* rowp = img + (size_t)(y + 1) * W;

    float a[6], b[6], c[6];
    load6(rowm, x0, W, has_up, a);
    load6(row0, x0, W, true,   b);
    load6(rowp, x0, W, has_dn, c);

    const float rows_valid = 1.0f + (has_up ? 1.0f : 0.0f) + (has_dn ? 1.0f : 0.0f);

    float4 res;
    float* rp = reinterpret_cast<float*>(&res);

    #pragma unroll
    for (int i = 0; i < 4; i++) {
        const int x = x0 + i;
        const bool has_l = (x > 0);
        const bool has_r = (x < W - 1);

        // 3x3 zero-padded sum
        const float sum9 = (a[i] + a[i + 1] + a[i + 2])
                         + (b[i] + b[i + 1] + b[i + 2])
                         + (c[i] + c[i + 1] + c[i + 2]);

        const float cols_valid = 1.0f + (has_l ? 1.0f : 0.0f) + (has_r ? 1.0f : 0.0f);
        const float count = rows_valid * cols_valid;         // 9, 6 or 4
        const float coeff = 9.0f / count;                    // 1.0, 1.5, 2.25 (exact)
        const float mean  = (sum9 * (1.0f / 9.0f)) * coeff;  // matches ref box*coeff

        const float v = b[i + 1];
        const bool mask = (v > THRE_TIMES * mean) || (v > THRE_POINT);

        // 4-neighbor repair
        const float nsum = b[i] + b[i + 2] + a[i + 1] + c[i + 1];
        const float cnt  = (has_up ? 1.0f : 0.0f) + (has_dn ? 1.0f : 0.0f)
                         + (has_l  ? 1.0f : 0.0f) + (has_r  ? 1.0f : 0.0f);
        const float repaired = floorf(nsum / cnt);

        rp[i] = mask ? repaired : v;
    }

    *reinterpret_cast<float4*>(out + (size_t)y * W + x0) = res;
}

extern "C" void kernel_launch(void* const* d_in, const int* in_sizes, int n_in,
                              void* d_out, int out_size) {
    const float* img = (const float*)d_in[0];
    float* out = (float*)d_out;

    // square image; derive side from element count (8192 for this problem)
    long long n = in_sizes[0];
    int side = (int)(sqrt((double)n) + 0.5);
    const int H = side, W = side;

    dim3 block(32, 8);
    dim3 grid((W / 4 + block.x - 1) / block.x, (H + block.y - 1) / block.y);
    repair_kernel<<<grid, block>>>(img, out, H, W);
}

// round 2
// speedup vs baseline: 1.0018x; 1.0018x over previous
#include <cuda_runtime.h>
#include <math.h>

// DamagedPointRepair:
//   mean  = 3x3 zero-padded box mean * coeff  (== average over in-bounds 3x3 window)
//   mask  = img > 5*mean || img > 1000
//   nsum  = 4-neighbor sum (zero padded), cnt = # valid 4-neighbors
//   out   = mask ? floor(nsum/cnt) : img
//
// 8192 x 8192 fp32. Memory-bound stencil: target ~1x read + 1x write DRAM traffic.

#define THRE_TIMES 5.0f
#define THRE_POINT 1000.0f

__device__ __forceinline__ void load6(const float* __restrict__ row, int x0, int W,
                                      bool valid, float v[6]) {
    if (valid) {
        const float4 c = *reinterpret_cast<const float4*>(row + x0);
        v[1] = c.x; v[2] = c.y; v[3] = c.z; v[4] = c.w;
        v[0] = (x0 > 0)       ? __ldg(row + x0 - 1) : 0.0f;
        v[5] = (x0 + 4 < W)   ? __ldg(row + x0 + 4) : 0.0f;
    } else {
        v[0] = v[1] = v[2] = v[3] = v[4] = v[5] = 0.0f;
    }
}

__global__ void __launch_bounds__(256)
repair_kernel(const float* __restrict__ img, float* __restrict__ out,
              int H, int W) {
    const int x0 = (blockIdx.x * blockDim.x + threadIdx.x) * 4;
    const int y  = blockIdx.y * blockDim.y + threadIdx.y;
    if (x0 >= W || y >= H) return;

    const bool has_up = (y > 0);
    const bool has_dn = (y < H - 1);

    const float* rowm = img + (size_t)(y - 1) * W;
    const float* row0 = img + (size_t)y * W;
    const float* rowp = img + (size_t)(y + 1) * W;

    float a[6], b[6], c[6];
    load6(rowm, x0, W, has_up, a);
    load6(row0, x0, W, true,   b);
    load6(rowp, x0, W, has_dn, c);

    const float rows_valid = 1.0f + (has_up ? 1.0f : 0.0f) + (has_dn ? 1.0f : 0.0f);

    float4 res;
    float* rp = reinterpret_cast<float*>(&res);

    #pragma unroll
    for (int i = 0; i < 4; i++) {
        const int x = x0 + i;
        const bool has_l = (x > 0);
        const bool has_r = (x < W - 1);

        // 3x3 zero-padded sum
        const float sum9 = (a[i] + a[i + 1] + a[i + 2])
                         + (b[i] + b[i + 1] + b[i + 2])
                         + (c[i] + c[i + 1] + c[i + 2]);

        const float cols_valid = 1.0f + (has_l ? 1.0f : 0.0f) + (has_r ? 1.0f : 0.0f);
        const float count = rows_valid * cols_valid;         // 9, 6 or 4
        const float coeff = 9.0f / count;                    // 1.0, 1.5, 2.25 (exact)
        const float mean  = (sum9 * (1.0f / 9.0f)) * coeff;  // matches ref box*coeff

        const float v = b[i + 1];
        const bool mask = (v > THRE_TIMES * mean) || (v > THRE_POINT);

        // 4-neighbor repair
        const float nsum = b[i] + b[i + 2] + a[i + 1] + c[i + 1];
        const float cnt  = (has_up ? 1.0f : 0.0f) + (has_dn ? 1.0f : 0.0f)
                         + (has_l  ? 1.0f : 0.0f) + (has_r  ? 1.0f : 0.0f);
        const float repaired = floorf(nsum / cnt);

        rp[i] = mask ? repaired : v;
    }

    *reinterpret_cast<float4*>(out + (size_t)y * W + x0) = res;
}

extern "C" void kernel_launch(void* const* d_in, const int* in_sizes, int n_in,
                              void* d_out, int out_size) {
    const float* img = (const float*)d_in[0];
    float* out = (float*)d_out;

    // square image; derive side from element count (8192 for this problem)
    long long n = in_sizes[0];
    int side = (int)(sqrt((double)n) + 0.5);
    const int H = side, W = side;

    dim3 block(32, 8);
    dim3 grid((W / 4 + block.x - 1) / block.x, (H + block.y - 1) / block.y);
    repair_kernel<<<grid, block>>>(img, out, H, W);
}